// round 5
// baseline (speedup 1.0000x reference)
#include <cuda_runtime.h>
#include <math.h>

#define NB 16
#define NN 2048
#define NK 20
#define NC 64
#define TP 64          // points per CTA tile

typedef unsigned long long u64;

// ---- scratch (static __device__, allocation-free) ----
__device__ int   g_idxT[NB*NK*NN];          // knn indices, [b][k][n]
__device__ float g_bxT [NB*NN*NC];          // act_g * (basis_W @ x), point-major [p][c]
__device__ float g_cst [NB*NN*NC];          // edge_g*((We2-We1)@x) + edge_be, [p][o]
__device__ float g_apT [NB*NK*8*NN];        // appf transposed to [b][k][c][n]
__device__ float g_glT [NB*NK*32*NN];       // glf  transposed to [b][k][c][n]

// ---- packed f32x2 helpers (Blackwell FFMA2) ----
__device__ __forceinline__ u64 f2pack(float lo, float hi) {
    u64 r; asm("mov.b64 %0, {%1, %2};" : "=l"(r) : "f"(lo), "f"(hi)); return r;
}
__device__ __forceinline__ void f2unpack(u64 v, float& lo, float& hi) {
    asm("mov.b64 {%0, %1}, %2;" : "=f"(lo), "=f"(hi) : "l"(v));
}
__device__ __forceinline__ void ffma2(u64& d, u64 a, u64 b) {
    asm("fma.rn.f32x2 %0, %1, %2, %3;" : "=l"(d) : "l"(a), "l"(b), "l"(d));
}

// =====================================================================
// KNN: per (b,q) top-20 by pd = 2<pq,pm> - |pq|^2 - |pm|^2 (excl self)
// =====================================================================
__global__ void knn_kernel(const float* __restrict__ pos)
{
    __shared__ float4 sp[NN];
    const int b   = blockIdx.y;
    const int tid = threadIdx.x;
    const float* pb = pos + (size_t)b*3*NN;
    for (int m = tid; m < NN; m += blockDim.x) {
        float x = pb[m], y = pb[NN + m], z = pb[2*NN + m];
        sp[m] = make_float4(x, y, z, x*x + y*y + z*z);
    }
    __syncthreads();
    const int q = blockIdx.x * blockDim.x + tid;
    const float4 pq = sp[q];

    float tv[NK]; int ti[NK];
    #pragma unroll
    for (int i = 0; i < NK; i++) { tv[i] = -1e30f; ti[i] = 0; }

    #pragma unroll 1
    for (int m = 0; m < NN; m++) {
        if (m == q) continue;
        float4 pm = sp[m];
        float pd = 2.0f*(pq.x*pm.x + pq.y*pm.y + pq.z*pm.z) - pq.w - pm.w;
        if (pd > tv[NK-1]) {
            tv[NK-1] = pd; ti[NK-1] = m;
            #pragma unroll
            for (int i = NK-1; i > 0; i--) {
                if (tv[i] > tv[i-1]) {       // strict: ties keep lower index first
                    float fv = tv[i-1]; tv[i-1] = tv[i]; tv[i] = fv;
                    int   iv = ti[i-1]; ti[i-1] = ti[i]; ti[i] = iv;
                }
            }
        }
    }
    #pragma unroll
    for (int i = 0; i < NK; i++)
        g_idxT[((size_t)b*NK + i)*NN + q] = ti[i];
}

// =====================================================================
// prep: g_bxT[p][c] = act_g[c] * (basis_W @ x)[c]
//       g_cst[p][o] = edge_g[o] * ((We2-We1)@x)[o] + edge_be[o]
// =====================================================================
__global__ void prep_kernel(const float* __restrict__ x,
                            const float* __restrict__ basis_W,
                            const float* __restrict__ edge_W,
                            const float* __restrict__ act_g,
                            const float* __restrict__ edge_g,
                            const float* __restrict__ edge_be)
{
    __shared__ float sB[64*64];
    __shared__ float sD[64*64];
    __shared__ float sag[64], seg[64], seb[64];
    const int tid = threadIdx.x;
    for (int i = tid; i < 4096; i += blockDim.x) {
        sB[i] = basis_W[i];
        int o = i >> 6, c = i & 63;
        sD[i] = edge_W[o*128 + 64 + c] - edge_W[o*128 + c];
    }
    for (int i = tid; i < 64; i += blockDim.x) {
        sag[i] = act_g[i]; seg[i] = edge_g[i]; seb[i] = edge_be[i];
    }
    __syncthreads();

    const int p = blockIdx.x * blockDim.x + tid;
    const int b = p / NN, n = p % NN;
    const float* xp = x + (size_t)b*64*NN + n;
    float xv[64];
    #pragma unroll
    for (int c = 0; c < 64; c++) xv[c] = xp[(size_t)c*NN];

    float* bo = g_bxT + (size_t)p*64;
    #pragma unroll 4
    for (int o = 0; o < 64; o++) {
        float acc = 0.f;
        #pragma unroll
        for (int c = 0; c < 64; c++) acc += sB[o*64+c]*xv[c];
        bo[o] = acc * sag[o];
    }
    float* co = g_cst + (size_t)p*64;
    #pragma unroll 4
    for (int o = 0; o < 64; o++) {
        float acc = 0.f;
        #pragma unroll
        for (int c = 0; c < 64; c++) acc += sD[o*64+c]*xv[c];
        co[o] = acc*seg[o] + seb[o];
    }
}

// =====================================================================
// combined transpose kernel:
//   blockIdx.y <  32 : glf (B,32,N,K) -> [b][k][c][n], c = blockIdx.y
//   blockIdx.y == 32 : appf (B,N,K,8) -> [b][k][c][n]
// tile = 64 n, block = 256 threads
// =====================================================================
__global__ void tr_kernel(const float* __restrict__ glf,
                          const float* __restrict__ appf)
{
    const int n0 = blockIdx.x * 64;
    const int b  = blockIdx.z;
    const int tid = threadIdx.x;
    if (blockIdx.y < 32) {
        __shared__ float s[64*21];
        const int c = blockIdx.y;
        const float* in = glf + (((size_t)b*32 + c)*NN + n0) * NK;
        #pragma unroll
        for (int u = 0; u < 5; u++) {
            int f = tid + u*256;                 // 1280 total
            int n = f / 20, k = f % 20;
            s[n*21 + k] = in[f];
        }
        __syncthreads();
        #pragma unroll
        for (int u = 0; u < 5; u++) {
            int f = tid + u*256;
            int k = f >> 6, n = f & 63;
            g_glT[(((size_t)b*NK + k)*32 + c)*NN + n0 + n] = s[n*21 + k];
        }
    } else {
        __shared__ float s2[64*161];
        const float* in = appf + ((size_t)b*NN + n0) * (NK*8);
        #pragma unroll
        for (int u = 0; u < 40; u++) {
            int f = tid + u*256;                 // 10240 total
            int n = f / 160, r = f % 160;
            s2[n*161 + r] = in[f];
        }
        __syncthreads();
        #pragma unroll
        for (int u = 0; u < 40; u++) {
            int f = tid + u*256;
            int row = f >> 6, n = f & 63;        // row = k*8+c
            g_apT[((size_t)b*NK*8 + row)*NN + n0 + n] = s2[n*161 + row];
        }
    }
}

// =====================================================================
// main fused kernel: CTA = 256 threads, 64-point tile, 2 points/thread.
// GEMM inner loops use packed fma.rn.f32x2 (o-pair accumulators).
// =====================================================================
#define LEAKY(v) ((v) > 0.f ? (v) : 0.2f*(v))

__global__ void __launch_bounds__(256, 2)
main_kernel(const float* __restrict__ dk_W1, const float* __restrict__ dk_b1,
            const float* __restrict__ dk_g1, const float* __restrict__ dk_be1,
            const float* __restrict__ dk_W2, const float* __restrict__ dk_b2,
            const float* __restrict__ act_b,
            const float* __restrict__ ff_W1, const float* __restrict__ ff_g1,
            const float* __restrict__ ff_be1, const float* __restrict__ ff_W2,
            const float* __restrict__ edge_W, const float* __restrict__ edge_g,
            float* __restrict__ out)
{
    extern __shared__ float sm[];
    float* wW1t = sm;             // [8][16]   128
    float* wb1  = wW1t + 128;     // 16
    float* wW2t = wb1  + 16;      // [16][32]  512
    float* wb2  = wW2t + 512;     // 32
    float* wF1t = wb2  + 32;      // [64][32]  2048
    float* wbf  = wF1t + 2048;    // 32
    float* wF2t = wbf  + 32;      // [32][64]  2048
    float* wab  = wF2t + 2048;    // 64
    float* wWEt = wab  + 64;      // [64][64]  4096
    float* t_in = wWEt + 4096;    // [8][64]   512
    float* t_h  = t_in + 512;     // [16][64]  1024
    float* t_rif= t_h  + 1024;    // [64][64]  4096 (becomes feat in place)
    float* t_att= t_rif+ 4096;    // [32][64]  2048
    int*   s_idx= (int*)(t_att + 2048);   // 64

    const int tid = threadIdx.x;
    const int w   = tid >> 5;
    const int l   = tid & 31;
    const int p0  = l*2;
    const int b   = blockIdx.x >> 5;
    const int n0  = (blockIdx.x & 31) << 6;

    // ---- stage folded, transposed weights ----
    for (int i = tid; i < 128; i += 256) { int c=i>>4, o=i&15; wW1t[i] = dk_g1[o]*dk_W1[o*8+c]; }
    if (tid < 16) wb1[tid] = dk_g1[tid]*dk_b1[tid] + dk_be1[tid];
    for (int i = tid; i < 512; i += 256) { int c=i>>5, o=i&31; wW2t[i] = dk_W2[o*16+c]; }
    if (tid < 32) wb2[tid] = dk_b2[tid];
    for (int i = tid; i < 2048; i += 256) { int c=i>>5, o=i&31; wF1t[i] = ff_g1[o]*ff_W1[o*64+c]; }
    if (tid < 32) wbf[tid] = ff_be1[tid];
    for (int i = tid; i < 2048; i += 256) { int c=i>>6, o=i&63; wF2t[i] = ff_W2[o*32+c]; }
    if (tid < 64) wab[tid] = act_b[tid];
    for (int i = tid; i < 4096; i += 256) { int c=i>>6, o=i&63; wWEt[i] = edge_g[o]*edge_W[o*128+c]; }
    __syncthreads();

    float mx[2][8];                         // [point][o]
    #pragma unroll
    for (int pp = 0; pp < 2; pp++)
        #pragma unroll
        for (int oo = 0; oo < 8; oo++) mx[pp][oo] = -1e30f;

    #pragma unroll 1
    for (int k = 0; k < NK; k++) {
        // ---- stage input tiles (coalesced) ----
        {
            const float* src = g_apT + (((size_t)b*NK + k)*8)*NN + n0;
            int f = tid*2;                       // 512 floats
            int c = f >> 6, col = f & 63;
            *(float2*)&t_in[f] = *(const float2*)&src[c*NN + col];
        }
        {
            const float* src = g_glT + (((size_t)b*NK + k)*32)*NN + n0;
            #pragma unroll
            for (int u = 0; u < 2; u++) {
                int f = (tid + u*256)*4;         // 2048 floats
                int c = f >> 6, col = f & 63;
                *(float4*)&t_rif[(32+c)*64 + col] = *(const float4*)&src[c*NN + col];
            }
        }
        if (tid < 64) s_idx[tid] = g_idxT[((size_t)b*NK + k)*NN + n0 + tid];
        __syncthreads();

        // ---- GEMM1: dk1 [16x64], K=8, warp owns o-pair (2o) x 64p ----
        {
            const int o0 = w*2;
            const u64 bias = *(const u64*)&wb1[o0];
            u64 a0 = bias, a1 = bias;
            #pragma unroll
            for (int c = 0; c < 8; c++) {
                u64 wv = *(const u64*)&wW1t[c*16 + o0];
                float2 bv = *(float2*)&t_in[c*64 + p0];
                ffma2(a0, wv, f2pack(bv.x, bv.x));
                ffma2(a1, wv, f2pack(bv.y, bv.y));
            }
            float l0,h0,l1,h1;
            f2unpack(a0,l0,h0); f2unpack(a1,l1,h1);
            *(float2*)&t_h[o0*64 + p0]     = make_float2(fmaxf(l0,0.f), fmaxf(l1,0.f));
            *(float2*)&t_h[(o0+1)*64 + p0] = make_float2(fmaxf(h0,0.f), fmaxf(h1,0.f));
        }
        __syncthreads();

        // ---- GEMM2: dk2 [32x64], K=16, 4o x 2p ----
        {
            const int o0 = w*4;
            ulonglong2 bi = *(const ulonglong2*)&wb2[o0];
            u64 acc[2][2];
            #pragma unroll
            for (int pp = 0; pp < 2; pp++) { acc[pp][0] = bi.x; acc[pp][1] = bi.y; }
            #pragma unroll
            for (int c = 0; c < 16; c++) {
                ulonglong2 wv = *(const ulonglong2*)&wW2t[c*32 + o0];
                float2 bv = *(float2*)&t_h[c*64 + p0];
                u64 bx = f2pack(bv.x,bv.x), by = f2pack(bv.y,bv.y);
                ffma2(acc[0][0], wv.x, bx); ffma2(acc[0][1], wv.y, bx);
                ffma2(acc[1][0], wv.x, by); ffma2(acc[1][1], wv.y, by);
            }
            #pragma unroll
            for (int pr = 0; pr < 2; pr++) {
                float l0,h0,l1,h1;
                f2unpack(acc[0][pr],l0,h0); f2unpack(acc[1][pr],l1,h1);
                *(float2*)&t_rif[(o0+2*pr)*64 + p0]   = make_float2(l0,l1);
                *(float2*)&t_rif[(o0+2*pr+1)*64 + p0] = make_float2(h0,h1);
            }
        }
        __syncthreads();

        // ---- GEMM3: ff1 [32x64], K=64, 4o x 2p, leaky(bn) ----
        {
            const int o0 = w*4;
            ulonglong2 bi = *(const ulonglong2*)&wbf[o0];
            u64 acc[2][2];
            #pragma unroll
            for (int pp = 0; pp < 2; pp++) { acc[pp][0] = bi.x; acc[pp][1] = bi.y; }
            #pragma unroll 8
            for (int c = 0; c < 64; c++) {
                ulonglong2 wv = *(const ulonglong2*)&wF1t[c*32 + o0];
                float2 bv = *(float2*)&t_rif[c*64 + p0];
                u64 bx = f2pack(bv.x,bv.x), by = f2pack(bv.y,bv.y);
                ffma2(acc[0][0], wv.x, bx); ffma2(acc[0][1], wv.y, bx);
                ffma2(acc[1][0], wv.x, by); ffma2(acc[1][1], wv.y, by);
            }
            #pragma unroll
            for (int pr = 0; pr < 2; pr++) {
                float l0,h0,l1,h1;
                f2unpack(acc[0][pr],l0,h0); f2unpack(acc[1][pr],l1,h1);
                *(float2*)&t_att[(o0+2*pr)*64 + p0]   = make_float2(LEAKY(l0),LEAKY(l1));
                *(float2*)&t_att[(o0+2*pr+1)*64 + p0] = make_float2(LEAKY(h0),LEAKY(h1));
            }
        }
        __syncthreads();

        // ---- GEMM4: ff2 [64x64], K=32, 8o x 2p; sigmoid; gate in place ----
        {
            const int o0 = w*8;
            u64 acc[2][4];
            #pragma unroll
            for (int pp = 0; pp < 2; pp++)
                #pragma unroll
                for (int pr = 0; pr < 4; pr++) acc[pp][pr] = 0ull;
            #pragma unroll 8
            for (int c = 0; c < 32; c++) {
                ulonglong2 wA = *(const ulonglong2*)&wF2t[c*64 + o0];
                ulonglong2 wB = *(const ulonglong2*)&wF2t[c*64 + o0 + 4];
                float2 bv = *(float2*)&t_att[c*64 + p0];
                u64 bx = f2pack(bv.x,bv.x), by = f2pack(bv.y,bv.y);
                ffma2(acc[0][0], wA.x, bx); ffma2(acc[0][1], wA.y, bx);
                ffma2(acc[0][2], wB.x, bx); ffma2(acc[0][3], wB.y, bx);
                ffma2(acc[1][0], wA.x, by); ffma2(acc[1][1], wA.y, by);
                ffma2(acc[1][2], wB.x, by); ffma2(acc[1][3], wB.y, by);
            }
            // gate in two o-halves to bound register pressure
            #pragma unroll
            for (int hh = 0; hh < 2; hh++) {
                float sg[2][4];
                float bxv[2][4];
                #pragma unroll
                for (int pp = 0; pp < 2; pp++) {
                    float lo, hi;
                    f2unpack(acc[pp][2*hh],   lo, hi);
                    sg[pp][0] = 1.f/(1.f + __expf(-lo));
                    sg[pp][1] = 1.f/(1.f + __expf(-hi));
                    f2unpack(acc[pp][2*hh+1], lo, hi);
                    sg[pp][2] = 1.f/(1.f + __expf(-lo));
                    sg[pp][3] = 1.f/(1.f + __expf(-hi));
                    int j = s_idx[p0 + pp];
                    float4 gv = *(const float4*)(g_bxT + ((size_t)b*NN + j)*64 + o0 + 4*hh);
                    bxv[pp][0] = gv.x; bxv[pp][1] = gv.y; bxv[pp][2] = gv.z; bxv[pp][3] = gv.w;
                }
                #pragma unroll
                for (int oo = 0; oo < 4; oo++) {
                    int row = o0 + 4*hh + oo;
                    float ab = wab[row];
                    float2 rv = *(float2*)&t_rif[row*64 + p0];
                    rv.x = fmaxf(rv.x * sg[0][oo] * bxv[0][oo] + ab, 0.f);
                    rv.y = fmaxf(rv.y * sg[1][oo] * bxv[1][oo] + ab, 0.f);
                    *(float2*)&t_rif[row*64 + p0] = rv;
                }
            }
        }
        __syncthreads();

        // ---- GEMM5: edge [64x64], K=64, 8o x 2p; running max (leaky+cst deferred) ----
        {
            const int o0 = w*8;
            u64 acc[2][4];
            #pragma unroll
            for (int pp = 0; pp < 2; pp++)
                #pragma unroll
                for (int pr = 0; pr < 4; pr++) acc[pp][pr] = 0ull;
            #pragma unroll 8
            for (int c = 0; c < 64; c++) {
                ulonglong2 wA = *(const ulonglong2*)&wWEt[c*64 + o0];
                ulonglong2 wB = *(const ulonglong2*)&wWEt[c*64 + o0 + 4];
                float2 bv = *(float2*)&t_rif[c*64 + p0];
                u64 bx = f2pack(bv.x,bv.x), by = f2pack(bv.y,bv.y);
                ffma2(acc[0][0], wA.x, bx); ffma2(acc[0][1], wA.y, bx);
                ffma2(acc[0][2], wB.x, bx); ffma2(acc[0][3], wB.y, bx);
                ffma2(acc[1][0], wA.x, by); ffma2(acc[1][1], wA.y, by);
                ffma2(acc[1][2], wB.x, by); ffma2(acc[1][3], wB.y, by);
            }
            #pragma unroll
            for (int pp = 0; pp < 2; pp++) {
                #pragma unroll
                for (int pr = 0; pr < 4; pr++) {
                    float lo, hi;
                    f2unpack(acc[pp][pr], lo, hi);
                    mx[pp][2*pr]   = fmaxf(mx[pp][2*pr],   lo);
                    mx[pp][2*pr+1] = fmaxf(mx[pp][2*pr+1], hi);
                }
            }
        }
        __syncthreads();
    }

    // ---- epilogue: out = leaky(mx + cst), write coalesced along n ----
    {
        const int o0 = w*8;
        #pragma unroll
        for (int hh = 0; hh < 2; hh++) {
            float cc[2][4];
            #pragma unroll
            for (int pp = 0; pp < 2; pp++) {
                float4 cv = *(const float4*)(g_cst + ((size_t)b*NN + n0 + p0 + pp)*64 + o0 + 4*hh);
                cc[pp][0]=cv.x; cc[pp][1]=cv.y; cc[pp][2]=cv.z; cc[pp][3]=cv.w;
            }
            #pragma unroll
            for (int oo = 0; oo < 4; oo++) {
                int row = o0 + 4*hh + oo;
                float2 v;
                v.x = LEAKY(mx[0][4*hh+oo] + cc[0][oo]);
                v.y = LEAKY(mx[1][4*hh+oo] + cc[1][oo]);
                *(float2*)&out[((size_t)b*64 + row)*NN + n0 + p0] = v;
            }
        }
    }
}

// =====================================================================
extern "C" void kernel_launch(void* const* d_in, const int* in_sizes, int n_in,
                              void* d_out, int out_size)
{
    const float* pos     = (const float*)d_in[0];
    const float* x       = (const float*)d_in[1];
    const float* glf     = (const float*)d_in[2];
    const float* appf    = (const float*)d_in[3];
    const float* basis_W = (const float*)d_in[4];
    const float* dk_W1   = (const float*)d_in[5];
    const float* dk_b1   = (const float*)d_in[6];
    const float* dk_g1   = (const float*)d_in[7];
    const float* dk_be1  = (const float*)d_in[8];
    const float* dk_W2   = (const float*)d_in[9];
    const float* dk_b2   = (const float*)d_in[10];
    const float* act_g   = (const float*)d_in[11];
    const float* act_b   = (const float*)d_in[12];
    const float* ff_W1   = (const float*)d_in[13];
    const float* ff_g1   = (const float*)d_in[14];
    const float* ff_be1  = (const float*)d_in[15];
    const float* ff_W2   = (const float*)d_in[16];
    const float* edge_W  = (const float*)d_in[17];
    const float* edge_g  = (const float*)d_in[18];
    const float* edge_be = (const float*)d_in[19];
    float* out = (float*)d_out;

    knn_kernel<<<dim3(NN/256, NB), 256>>>(pos);
    prep_kernel<<<(NB*NN)/128, 128>>>(x, basis_W, edge_W, act_g, edge_g, edge_be);
    tr_kernel<<<dim3(NN/64, 33, NB), 256>>>(glf, appf);

    const int smem_bytes = (8976 + 512 + 1024 + 4096 + 2048 + 64) * (int)sizeof(float);
    cudaFuncSetAttribute(main_kernel, cudaFuncAttributeMaxDynamicSharedMemorySize, smem_bytes);
    main_kernel<<<NB*NN/TP, 256, smem_bytes>>>(dk_W1, dk_b1, dk_g1, dk_be1,
                                               dk_W2, dk_b2, act_b,
                                               ff_W1, ff_g1, ff_be1, ff_W2,
                                               edge_W, edge_g, out);
}

// round 6
// speedup vs baseline: 1.1820x; 1.1820x over previous
#include <cuda_runtime.h>
#include <math.h>

#define NB 16
#define NN 2048
#define NK 20
#define NC 64

typedef unsigned long long u64;

// ---- scratch (static __device__, allocation-free) ----
__device__ int   g_idxT[NB*NK*NN];          // knn indices, [b][k][n]
__device__ float g_bxT [NB*NN*NC];          // act_g * (basis_W @ x), point-major [p][c]
__device__ float g_cst [NB*NN*NC];          // edge_g*((We2-We1)@x) + edge_be, [p][o]
__device__ float g_apT [NB*NK*8*NN];        // appf transposed to [b][k][c][n]
__device__ float g_glT [NB*NK*32*NN];       // glf  transposed to [b][k][c][n]

// ---- packed f32x2 helpers (Blackwell FFMA2) ----
__device__ __forceinline__ u64 f2pack(float lo, float hi) {
    u64 r; asm("mov.b64 %0, {%1, %2};" : "=l"(r) : "f"(lo), "f"(hi)); return r;
}
__device__ __forceinline__ void f2unpack(u64 v, float& lo, float& hi) {
    asm("mov.b64 {%0, %1}, %2;" : "=f"(lo), "=f"(hi) : "l"(v));
}
__device__ __forceinline__ void ffma2(u64& d, u64 a, u64 b) {
    asm("fma.rn.f32x2 %0, %1, %2, %3;" : "=l"(d) : "l"(a), "l"(b), "l"(d));
}

// =====================================================================
// KNN: per (b,q) top-20 by pd = 2<pq,pm> - |pq|^2 - |pm|^2 (excl self)
// Branchless predicated ripple insert (no divergent BSSY chains).
// =====================================================================
__global__ void __launch_bounds__(128)
knn_kernel(const float* __restrict__ pos)
{
    __shared__ float4 sp[NN];
    const int b   = blockIdx.y;
    const int tid = threadIdx.x;
    const float* pb = pos + (size_t)b*3*NN;
    for (int m = tid; m < NN; m += blockDim.x) {
        float x = pb[m], y = pb[NN + m], z = pb[2*NN + m];
        sp[m] = make_float4(x, y, z, x*x + y*y + z*z);
    }
    __syncthreads();
    const int q = blockIdx.x * blockDim.x + tid;
    const float4 pq = sp[q];

    float tv[NK]; int ti[NK];
    #pragma unroll
    for (int i = 0; i < NK; i++) { tv[i] = -1e30f; ti[i] = 0; }

    #pragma unroll 2
    for (int m = 0; m < NN; m++) {
        float4 pm = sp[m];
        float pd = 2.0f*(pq.x*pm.x + pq.y*pm.y + pq.z*pm.z) - pq.w - pm.w;
        pd = (m == q) ? -1e30f : pd;         // exclude self via select, no branch
        if (pd > tv[NK-1]) {
            // branchless sorted insert: unique position where
            // (pd <= tv[i-1]) && (pd > tv[i]); rows above shift down.
            // strict > keeps existing (lower-index) entries above on ties.
            #pragma unroll
            for (int i = NK-1; i >= 1; i--) {
                bool cp = pd > tv[i-1];
                bool cc = pd > tv[i];
                float nv = cp ? tv[i-1] : (cc ? pd : tv[i]);
                int   ni = cp ? ti[i-1] : (cc ? m  : ti[i]);
                tv[i] = nv; ti[i] = ni;
            }
            bool c0 = pd > tv[0];
            tv[0] = c0 ? pd : tv[0];
            ti[0] = c0 ? m  : ti[0];
        }
    }
    #pragma unroll
    for (int i = 0; i < NK; i++)
        g_idxT[((size_t)b*NK + i)*NN + q] = ti[i];
}

// =====================================================================
// prep: g_bxT[p][c] = act_g[c] * (basis_W @ x)[c]
//       g_cst[p][o] = edge_g[o] * ((We2-We1)@x)[o] + edge_be[o]
// =====================================================================
__global__ void prep_kernel(const float* __restrict__ x,
                            const float* __restrict__ basis_W,
                            const float* __restrict__ edge_W,
                            const float* __restrict__ act_g,
                            const float* __restrict__ edge_g,
                            const float* __restrict__ edge_be)
{
    __shared__ float sB[64*64];
    __shared__ float sD[64*64];
    __shared__ float sag[64], seg[64], seb[64];
    const int tid = threadIdx.x;
    for (int i = tid; i < 4096; i += blockDim.x) {
        sB[i] = basis_W[i];
        int o = i >> 6, c = i & 63;
        sD[i] = edge_W[o*128 + 64 + c] - edge_W[o*128 + c];
    }
    for (int i = tid; i < 64; i += blockDim.x) {
        sag[i] = act_g[i]; seg[i] = edge_g[i]; seb[i] = edge_be[i];
    }
    __syncthreads();

    const int p = blockIdx.x * blockDim.x + tid;
    const int b = p / NN, n = p % NN;
    const float* xp = x + (size_t)b*64*NN + n;
    float xv[64];
    #pragma unroll
    for (int c = 0; c < 64; c++) xv[c] = xp[(size_t)c*NN];

    float* bo = g_bxT + (size_t)p*64;
    #pragma unroll 4
    for (int o = 0; o < 64; o++) {
        float acc = 0.f;
        #pragma unroll
        for (int c = 0; c < 64; c++) acc += sB[o*64+c]*xv[c];
        bo[o] = acc * sag[o];
    }
    float* co = g_cst + (size_t)p*64;
    #pragma unroll 4
    for (int o = 0; o < 64; o++) {
        float acc = 0.f;
        #pragma unroll
        for (int c = 0; c < 64; c++) acc += sD[o*64+c]*xv[c];
        co[o] = acc*seg[o] + seb[o];
    }
}

// =====================================================================
// combined transpose kernel:
//   blockIdx.y <  32 : glf (B,32,N,K) -> [b][k][c][n], c = blockIdx.y
//   blockIdx.y == 32 : appf (B,N,K,8) -> [b][k][c][n]
// tile = 64 n, block = 256 threads
// =====================================================================
__global__ void tr_kernel(const float* __restrict__ glf,
                          const float* __restrict__ appf)
{
    const int n0 = blockIdx.x * 64;
    const int b  = blockIdx.z;
    const int tid = threadIdx.x;
    if (blockIdx.y < 32) {
        __shared__ float s[64*21];
        const int c = blockIdx.y;
        const float* in = glf + (((size_t)b*32 + c)*NN + n0) * NK;
        #pragma unroll
        for (int u = 0; u < 5; u++) {
            int f = tid + u*256;                 // 1280 total
            int n = f / 20, k = f % 20;
            s[n*21 + k] = in[f];
        }
        __syncthreads();
        #pragma unroll
        for (int u = 0; u < 5; u++) {
            int f = tid + u*256;
            int k = f >> 6, n = f & 63;
            g_glT[(((size_t)b*NK + k)*32 + c)*NN + n0 + n] = s[n*21 + k];
        }
    } else {
        __shared__ float s2[64*161];
        const float* in = appf + ((size_t)b*NN + n0) * (NK*8);
        #pragma unroll
        for (int u = 0; u < 40; u++) {
            int f = tid + u*256;                 // 10240 total
            int n = f / 160, r = f % 160;
            s2[n*161 + r] = in[f];
        }
        __syncthreads();
        #pragma unroll
        for (int u = 0; u < 40; u++) {
            int f = tid + u*256;
            int row = f >> 6, n = f & 63;        // row = k*8+c
            g_apT[((size_t)b*NK*8 + row)*NN + n0 + n] = s2[n*161 + row];
        }
    }
}

// =====================================================================
// main fused kernel: CTA = 256 threads, 128-point tile, 4 points/thread.
// GEMM inner loops use packed fma.rn.f32x2 (o-pair accumulators).
// =====================================================================
#define LEAKY(v) ((v) > 0.f ? (v) : 0.2f*(v))

__global__ void __launch_bounds__(256, 2)
main_kernel(const float* __restrict__ dk_W1, const float* __restrict__ dk_b1,
            const float* __restrict__ dk_g1, const float* __restrict__ dk_be1,
            const float* __restrict__ dk_W2, const float* __restrict__ dk_b2,
            const float* __restrict__ act_b,
            const float* __restrict__ ff_W1, const float* __restrict__ ff_g1,
            const float* __restrict__ ff_be1, const float* __restrict__ ff_W2,
            const float* __restrict__ edge_W, const float* __restrict__ edge_g,
            float* __restrict__ out)
{
    extern __shared__ float sm[];
    float* wW1t = sm;             // [8][16]   128
    float* wb1  = wW1t + 128;     // 16
    float* wW2t = wb1  + 16;      // [16][32]  512
    float* wb2  = wW2t + 512;     // 32
    float* wF1t = wb2  + 32;      // [64][32]  2048
    float* wbf  = wF1t + 2048;    // 32
    float* wF2t = wbf  + 32;      // [32][64]  2048
    float* wab  = wF2t + 2048;    // 64
    float* wWEt = wab  + 64;      // [64][64]  4096
    float* t_in = wWEt + 4096;    // [8][128]  1024
    float* t_h  = t_in + 1024;    // [16][128] 2048
    float* t_rif= t_h  + 2048;    // [64][128] 8192 (becomes feat in place)
    float* t_att= t_rif+ 8192;    // [32][128] 4096
    int*   s_idx= (int*)(t_att + 4096);   // 128

    const int tid = threadIdx.x;
    const int w   = tid >> 5;
    const int l   = tid & 31;
    const int p0  = l*4;
    const int b   = blockIdx.x >> 4;
    const int n0  = (blockIdx.x & 15) << 7;

    // ---- stage folded, transposed weights ----
    for (int i = tid; i < 128; i += 256) { int c=i>>4, o=i&15; wW1t[i] = dk_g1[o]*dk_W1[o*8+c]; }
    if (tid < 16) wb1[tid] = dk_g1[tid]*dk_b1[tid] + dk_be1[tid];
    for (int i = tid; i < 512; i += 256) { int c=i>>5, o=i&31; wW2t[i] = dk_W2[o*16+c]; }
    if (tid < 32) wb2[tid] = dk_b2[tid];
    for (int i = tid; i < 2048; i += 256) { int c=i>>5, o=i&31; wF1t[i] = ff_g1[o]*ff_W1[o*64+c]; }
    if (tid < 32) wbf[tid] = ff_be1[tid];
    for (int i = tid; i < 2048; i += 256) { int c=i>>6, o=i&63; wF2t[i] = ff_W2[o*32+c]; }
    if (tid < 64) wab[tid] = act_b[tid];
    for (int i = tid; i < 4096; i += 256) { int c=i>>6, o=i&63; wWEt[i] = edge_g[o]*edge_W[o*128+c]; }
    __syncthreads();

    float mx[4][8];                         // [point][o]
    #pragma unroll
    for (int pp = 0; pp < 4; pp++)
        #pragma unroll
        for (int oo = 0; oo < 8; oo++) mx[pp][oo] = -1e30f;

    #pragma unroll 1
    for (int k = 0; k < NK; k++) {
        // ---- stage input tiles (coalesced) ----
        {
            const float* src = g_apT + (((size_t)b*NK + k)*8)*NN + n0;
            int f = tid*4;
            int c = f >> 7, col = f & 127;
            *(float4*)&t_in[f] = *(const float4*)&src[c*NN + col];
        }
        {
            const float* src = g_glT + (((size_t)b*NK + k)*32)*NN + n0;
            #pragma unroll
            for (int u = 0; u < 4; u++) {
                int f = (tid + u*256)*4;
                int c = f >> 7, col = f & 127;
                *(float4*)&t_rif[(32+c)*128 + col] = *(const float4*)&src[c*NN + col];
            }
        }
        if (tid < 128) s_idx[tid] = g_idxT[((size_t)b*NK + k)*NN + n0 + tid];
        __syncthreads();

        // ---- GEMM1: dk1 [16x128], K=8, warp owns o-pair (2o) x 128p ----
        {
            const int o0 = w*2;
            const u64 bias = *(const u64*)&wb1[o0];
            u64 a0 = bias, a1 = bias, a2 = bias, a3 = bias;
            #pragma unroll
            for (int c = 0; c < 8; c++) {
                u64 wv = *(const u64*)&wW1t[c*16 + o0];
                float4 bv = *(float4*)&t_in[c*128 + p0];
                ffma2(a0, wv, f2pack(bv.x, bv.x));
                ffma2(a1, wv, f2pack(bv.y, bv.y));
                ffma2(a2, wv, f2pack(bv.z, bv.z));
                ffma2(a3, wv, f2pack(bv.w, bv.w));
            }
            float l0,h0,l1,h1,l2,h2,l3,h3;
            f2unpack(a0,l0,h0); f2unpack(a1,l1,h1); f2unpack(a2,l2,h2); f2unpack(a3,l3,h3);
            float4 r0 = make_float4(fmaxf(l0,0.f), fmaxf(l1,0.f), fmaxf(l2,0.f), fmaxf(l3,0.f));
            float4 r1 = make_float4(fmaxf(h0,0.f), fmaxf(h1,0.f), fmaxf(h2,0.f), fmaxf(h3,0.f));
            *(float4*)&t_h[o0*128 + p0] = r0;
            *(float4*)&t_h[(o0+1)*128 + p0] = r1;
        }
        __syncthreads();

        // ---- GEMM2: dk2 [32x128], K=16, 4o x 4p, bias only ----
        {
            const int o0 = w*4;
            ulonglong2 bi = *(const ulonglong2*)&wb2[o0];
            u64 acc[4][2];
            #pragma unroll
            for (int pp = 0; pp < 4; pp++) { acc[pp][0] = bi.x; acc[pp][1] = bi.y; }
            #pragma unroll
            for (int c = 0; c < 16; c++) {
                ulonglong2 wv = *(const ulonglong2*)&wW2t[c*32 + o0];
                float4 bv = *(float4*)&t_h[c*128 + p0];
                u64 bx = f2pack(bv.x,bv.x), by = f2pack(bv.y,bv.y);
                u64 bz = f2pack(bv.z,bv.z), bw = f2pack(bv.w,bv.w);
                ffma2(acc[0][0], wv.x, bx); ffma2(acc[0][1], wv.y, bx);
                ffma2(acc[1][0], wv.x, by); ffma2(acc[1][1], wv.y, by);
                ffma2(acc[2][0], wv.x, bz); ffma2(acc[2][1], wv.y, bz);
                ffma2(acc[3][0], wv.x, bw); ffma2(acc[3][1], wv.y, bw);
            }
            #pragma unroll
            for (int pr = 0; pr < 2; pr++) {
                float l0,h0,l1,h1,l2,h2,l3,h3;
                f2unpack(acc[0][pr],l0,h0); f2unpack(acc[1][pr],l1,h1);
                f2unpack(acc[2][pr],l2,h2); f2unpack(acc[3][pr],l3,h3);
                *(float4*)&t_rif[(o0+2*pr)*128 + p0]   = make_float4(l0,l1,l2,l3);
                *(float4*)&t_rif[(o0+2*pr+1)*128 + p0] = make_float4(h0,h1,h2,h3);
            }
        }
        __syncthreads();

        // ---- GEMM3: ff1 [32x128], K=64, 4o x 4p, leaky(bn) ----
        {
            const int o0 = w*4;
            ulonglong2 bi = *(const ulonglong2*)&wbf[o0];
            u64 acc[4][2];
            #pragma unroll
            for (int pp = 0; pp < 4; pp++) { acc[pp][0] = bi.x; acc[pp][1] = bi.y; }
            #pragma unroll 4
            for (int c = 0; c < 64; c++) {
                ulonglong2 wv = *(const ulonglong2*)&wF1t[c*32 + o0];
                float4 bv = *(float4*)&t_rif[c*128 + p0];
                u64 bx = f2pack(bv.x,bv.x), by = f2pack(bv.y,bv.y);
                u64 bz = f2pack(bv.z,bv.z), bw = f2pack(bv.w,bv.w);
                ffma2(acc[0][0], wv.x, bx); ffma2(acc[0][1], wv.y, bx);
                ffma2(acc[1][0], wv.x, by); ffma2(acc[1][1], wv.y, by);
                ffma2(acc[2][0], wv.x, bz); ffma2(acc[2][1], wv.y, bz);
                ffma2(acc[3][0], wv.x, bw); ffma2(acc[3][1], wv.y, bw);
            }
            #pragma unroll
            for (int pr = 0; pr < 2; pr++) {
                float l0,h0,l1,h1,l2,h2,l3,h3;
                f2unpack(acc[0][pr],l0,h0); f2unpack(acc[1][pr],l1,h1);
                f2unpack(acc[2][pr],l2,h2); f2unpack(acc[3][pr],l3,h3);
                *(float4*)&t_att[(o0+2*pr)*128 + p0] =
                    make_float4(LEAKY(l0),LEAKY(l1),LEAKY(l2),LEAKY(l3));
                *(float4*)&t_att[(o0+2*pr+1)*128 + p0] =
                    make_float4(LEAKY(h0),LEAKY(h1),LEAKY(h2),LEAKY(h3));
            }
        }
        __syncthreads();

        // ---- GEMM4: ff2 [64x128], K=32, 8o x 4p; sigmoid; gate in place ----
        {
            const int o0 = w*8;
            u64 acc[4][4];
            #pragma unroll
            for (int pp = 0; pp < 4; pp++)
                #pragma unroll
                for (int pr = 0; pr < 4; pr++) acc[pp][pr] = 0ull;
            #pragma unroll 4
            for (int c = 0; c < 32; c++) {
                ulonglong2 wA = *(const ulonglong2*)&wF2t[c*64 + o0];
                ulonglong2 wB = *(const ulonglong2*)&wF2t[c*64 + o0 + 4];
                float4 bv = *(float4*)&t_att[c*128 + p0];
                u64 bx = f2pack(bv.x,bv.x), by = f2pack(bv.y,bv.y);
                u64 bz = f2pack(bv.z,bv.z), bw = f2pack(bv.w,bv.w);
                ffma2(acc[0][0], wA.x, bx); ffma2(acc[0][1], wA.y, bx);
                ffma2(acc[0][2], wB.x, bx); ffma2(acc[0][3], wB.y, bx);
                ffma2(acc[1][0], wA.x, by); ffma2(acc[1][1], wA.y, by);
                ffma2(acc[1][2], wB.x, by); ffma2(acc[1][3], wB.y, by);
                ffma2(acc[2][0], wA.x, bz); ffma2(acc[2][1], wA.y, bz);
                ffma2(acc[2][2], wB.x, bz); ffma2(acc[2][3], wB.y, bz);
                ffma2(acc[3][0], wA.x, bw); ffma2(acc[3][1], wA.y, bw);
                ffma2(acc[3][2], wB.x, bw); ffma2(acc[3][3], wB.y, bw);
            }
            // gate in two o-halves to bound register pressure
            #pragma unroll
            for (int hh = 0; hh < 2; hh++) {
                float sg[4][4];
                float bxv[4][4];
                #pragma unroll
                for (int pp = 0; pp < 4; pp++) {
                    float lo, hi;
                    f2unpack(acc[pp][2*hh],   lo, hi);
                    sg[pp][0] = 1.f/(1.f + __expf(-lo));
                    sg[pp][1] = 1.f/(1.f + __expf(-hi));
                    f2unpack(acc[pp][2*hh+1], lo, hi);
                    sg[pp][2] = 1.f/(1.f + __expf(-lo));
                    sg[pp][3] = 1.f/(1.f + __expf(-hi));
                    int j = s_idx[p0 + pp];
                    float4 gv = *(const float4*)(g_bxT + ((size_t)b*NN + j)*64 + o0 + 4*hh);
                    bxv[pp][0] = gv.x; bxv[pp][1] = gv.y; bxv[pp][2] = gv.z; bxv[pp][3] = gv.w;
                }
                #pragma unroll
                for (int oo = 0; oo < 4; oo++) {
                    int row = o0 + 4*hh + oo;
                    float ab = wab[row];
                    float4 rv = *(float4*)&t_rif[row*128 + p0];
                    rv.x = fmaxf(rv.x * sg[0][oo] * bxv[0][oo] + ab, 0.f);
                    rv.y = fmaxf(rv.y * sg[1][oo] * bxv[1][oo] + ab, 0.f);
                    rv.z = fmaxf(rv.z * sg[2][oo] * bxv[2][oo] + ab, 0.f);
                    rv.w = fmaxf(rv.w * sg[3][oo] * bxv[3][oo] + ab, 0.f);
                    *(float4*)&t_rif[row*128 + p0] = rv;
                }
            }
        }
        __syncthreads();

        // ---- GEMM5: edge [64x128], K=64, 8o x 4p; running max (leaky+cst deferred) ----
        {
            const int o0 = w*8;
            u64 acc[4][4];
            #pragma unroll
            for (int pp = 0; pp < 4; pp++)
                #pragma unroll
                for (int pr = 0; pr < 4; pr++) acc[pp][pr] = 0ull;
            #pragma unroll 4
            for (int c = 0; c < 64; c++) {
                ulonglong2 wA = *(const ulonglong2*)&wWEt[c*64 + o0];
                ulonglong2 wB = *(const ulonglong2*)&wWEt[c*64 + o0 + 4];
                float4 bv = *(float4*)&t_rif[c*128 + p0];
                u64 bx = f2pack(bv.x,bv.x), by = f2pack(bv.y,bv.y);
                u64 bz = f2pack(bv.z,bv.z), bw = f2pack(bv.w,bv.w);
                ffma2(acc[0][0], wA.x, bx); ffma2(acc[0][1], wA.y, bx);
                ffma2(acc[0][2], wB.x, bx); ffma2(acc[0][3], wB.y, bx);
                ffma2(acc[1][0], wA.x, by); ffma2(acc[1][1], wA.y, by);
                ffma2(acc[1][2], wB.x, by); ffma2(acc[1][3], wB.y, by);
                ffma2(acc[2][0], wA.x, bz); ffma2(acc[2][1], wA.y, bz);
                ffma2(acc[2][2], wB.x, bz); ffma2(acc[2][3], wB.y, bz);
                ffma2(acc[3][0], wA.x, bw); ffma2(acc[3][1], wA.y, bw);
                ffma2(acc[3][2], wB.x, bw); ffma2(acc[3][3], wB.y, bw);
            }
            #pragma unroll
            for (int pp = 0; pp < 4; pp++) {
                #pragma unroll
                for (int pr = 0; pr < 4; pr++) {
                    float lo, hi;
                    f2unpack(acc[pp][pr], lo, hi);
                    mx[pp][2*pr]   = fmaxf(mx[pp][2*pr],   lo);
                    mx[pp][2*pr+1] = fmaxf(mx[pp][2*pr+1], hi);
                }
            }
        }
        __syncthreads();
    }

    // ---- epilogue: out = leaky(mx + cst), write coalesced along n ----
    {
        const int o0 = w*8;
        #pragma unroll
        for (int hh = 0; hh < 2; hh++) {
            float cc[4][4];
            #pragma unroll
            for (int pp = 0; pp < 4; pp++) {
                float4 cv = *(const float4*)(g_cst + ((size_t)b*NN + n0 + p0 + pp)*64 + o0 + 4*hh);
                cc[pp][0]=cv.x; cc[pp][1]=cv.y; cc[pp][2]=cv.z; cc[pp][3]=cv.w;
            }
            #pragma unroll
            for (int oo = 0; oo < 4; oo++) {
                int row = o0 + 4*hh + oo;
                float4 v;
                v.x = LEAKY(mx[0][4*hh+oo] + cc[0][oo]);
                v.y = LEAKY(mx[1][4*hh+oo] + cc[1][oo]);
                v.z = LEAKY(mx[2][4*hh+oo] + cc[2][oo]);
                v.w = LEAKY(mx[3][4*hh+oo] + cc[3][oo]);
                *(float4*)&out[((size_t)b*64 + row)*NN + n0 + p0] = v;
            }
        }
    }
}

// =====================================================================
extern "C" void kernel_launch(void* const* d_in, const int* in_sizes, int n_in,
                              void* d_out, int out_size)
{
    const float* pos     = (const float*)d_in[0];
    const float* x       = (const float*)d_in[1];
    const float* glf     = (const float*)d_in[2];
    const float* appf    = (const float*)d_in[3];
    const float* basis_W = (const float*)d_in[4];
    const float* dk_W1   = (const float*)d_in[5];
    const float* dk_b1   = (const float*)d_in[6];
    const float* dk_g1   = (const float*)d_in[7];
    const float* dk_be1  = (const float*)d_in[8];
    const float* dk_W2   = (const float*)d_in[9];
    const float* dk_b2   = (const float*)d_in[10];
    const float* act_g   = (const float*)d_in[11];
    const float* act_b   = (const float*)d_in[12];
    const float* ff_W1   = (const float*)d_in[13];
    const float* ff_g1   = (const float*)d_in[14];
    const float* ff_be1  = (const float*)d_in[15];
    const float* ff_W2   = (const float*)d_in[16];
    const float* edge_W  = (const float*)d_in[17];
    const float* edge_g  = (const float*)d_in[18];
    const float* edge_be = (const float*)d_in[19];
    float* out = (float*)d_out;

    knn_kernel<<<dim3(NN/128, NB), 128>>>(pos);
    prep_kernel<<<(NB*NN)/128, 128>>>(x, basis_W, edge_W, act_g, edge_g, edge_be);
    tr_kernel<<<dim3(NN/64, 33, NB), 256>>>(glf, appf);

    const int smem_bytes = (128+16+512+32+2048+32+2048+64+4096 + 1024+2048+8192+4096 + 128) * (int)sizeof(float);
    cudaFuncSetAttribute(main_kernel, cudaFuncAttributeMaxDynamicSharedMemorySize, smem_bytes);
    main_kernel<<<NB*NN/128, 256, smem_bytes>>>(dk_W1, dk_b1, dk_g1, dk_be1,
                                                dk_W2, dk_b2, act_b,
                                                ff_W1, ff_g1, ff_be1, ff_W2,
                                                edge_W, edge_g, out);
}